// round 1
// baseline (speedup 1.0000x reference)
#include <cuda_runtime.h>
#include <cuda_bf16.h>
#include <cstddef>

// Problem shape (fixed for this problem instance):
//   logits [B, T, U+1, V] fp32, labels [B, U] int32, f_len [B], y_len [B]
#define Bk 8
#define Tk 256
#define Uk 64
#define U1k 65
#define Vk 1024
#define NEGF (-1e30f)

// Scratch (no allocations allowed -> device globals)
__device__ __align__(16) float g_blank[Bk * Tk * U1k];   // lp[..., 0]
__device__ __align__(16) float g_emit[Bk * Tk * Uk];     // lp[..., label], masked
__device__ float g_ll[Bk];

// ---------------------------------------------------------------------------
// Kernel 1: per-row logsumexp over V=1024; emit gather + length masking.
// One warp per (b,t,u) row. Each lane holds 32 values in registers
// (8x float4, stride-32 in float4 units => fully coalesced 128B transactions).
// ---------------------------------------------------------------------------
__global__ void __launch_bounds__(256) rnnt_softmax_kernel(
    const float* __restrict__ logits,
    const int* __restrict__ labels,
    const int* __restrict__ y_len)
{
    const int warp = (blockIdx.x * blockDim.x + threadIdx.x) >> 5;
    const int lane = threadIdx.x & 31;
    const int rows = Bk * Tk * U1k;
    if (warp >= rows) return;

    const int r = warp;
    const float4* p = reinterpret_cast<const float4*>(logits) + (size_t)r * (Vk / 4);

    float v[32];
    float m = NEGF;
#pragma unroll
    for (int k = 0; k < 8; ++k) {
        float4 f = p[lane + 32 * k];
        v[4 * k + 0] = f.x; v[4 * k + 1] = f.y;
        v[4 * k + 2] = f.z; v[4 * k + 3] = f.w;
        m = fmaxf(m, fmaxf(fmaxf(f.x, f.y), fmaxf(f.z, f.w)));
    }
#pragma unroll
    for (int o = 16; o; o >>= 1) m = fmaxf(m, __shfl_xor_sync(0xffffffffu, m, o));

    float s = 0.f;
#pragma unroll
    for (int i = 0; i < 32; ++i) s += __expf(v[i] - m);
#pragma unroll
    for (int o = 16; o; o >>= 1) s += __shfl_xor_sync(0xffffffffu, s, o);

    if (lane == 0) {
        const float lse = m + __logf(s);
        const int u  = r % U1k;
        const int bt = r / U1k;
        const int t  = bt % Tk;
        const int b  = bt / Tk;
        // element 0 lives in lane 0's v[0]
        g_blank[r] = v[0] - lse;
        if (u < Uk) {
            float e;
            if (u < y_len[b]) {
                const int lab = labels[b * Uk + u];
                // re-load one element; the row is resident in L1 of this SM
                e = __ldg(logits + (size_t)r * Vk + lab) - lse;
            } else {
                e = NEGF;
            }
            g_emit[(b * Tk + t) * Uk + u] = e;
        }
    }
}

// logaddexp, safe for very negative finite operands
__device__ __forceinline__ float lae(float x, float y) {
    const float mx = fmaxf(x, y);
    const float mn = fminf(x, y);
    return mx + __logf(1.0f + __expf(mn - mx));
}

// ---------------------------------------------------------------------------
// Kernel 2: wavefront DP. One block per batch element.
//   alpha[0,0]=0
//   alpha[0,u]   = alpha[0,u-1]   + emit[0,u-1]                         (cumsum)
//   alpha[t,0]   = alpha[t-1,0]   + blank[t-1,0]
//   alpha[t,u]   = logaddexp(alpha[t-1,u] + blank[t-1,u],
//                            alpha[t,u-1] + emit[t,u-1])
// Thread u keeps alpha[.,u] in a register; the left neighbor comes through a
// double-buffered shared line (1 barrier per anti-diagonal). blank/emit are
// staged wholesale into shared memory first (~130 KB) so the serial critical
// path only sees LDS latency.
// ---------------------------------------------------------------------------
__global__ void __launch_bounds__(128) rnnt_dp_kernel(
    const int* __restrict__ f_len,
    const int* __restrict__ y_len)
{
    extern __shared__ float sm[];
    float* s_blank = sm;                       // Tk*U1k
    float* s_emit  = sm + Tk * U1k;            // Tk*Uk
    float* comm    = sm + Tk * U1k + Tk * Uk;  // 2 * 66

    const int b   = blockIdx.x;
    const int tid = threadIdx.x;

    // Stage blank/emit for this batch into shared (vectorized, coalesced)
    {
        const float4* gb = reinterpret_cast<const float4*>(g_blank + b * Tk * U1k);
        float4* sb = reinterpret_cast<float4*>(s_blank);
        for (int i = tid; i < Tk * U1k / 4; i += blockDim.x) sb[i] = gb[i];
        const float4* ge = reinterpret_cast<const float4*>(g_emit + b * Tk * Uk);
        float4* se = reinterpret_cast<float4*>(s_emit);
        for (int i = tid; i < Tk * Uk / 4; i += blockDim.x) se[i] = ge[i];
    }
    __syncthreads();

    const int fl = f_len[b];
    const int yl = y_len[b];
    const int u  = tid;

    float a = (u == 0) ? 0.f : NEGF;  // alpha at this thread's column
    int p = 0;
    if (u < U1k) comm[u] = a;         // comm[0][*] holds diagonal d=0
    __syncthreads();

    for (int d = 1; d <= (Tk - 1) + Uk; ++d) {
        float left = NEGF;
        if (u >= 1 && u < U1k) left = comm[p * 66 + (u - 1)];

        if (u < U1k) {
            const int t = d - u;
            if (t >= 1 && t < Tk) {
                if (u == 0) {
                    a = a + s_blank[(t - 1) * U1k];
                } else {
                    const float x = a + s_blank[(t - 1) * U1k + u];
                    const float y = left + s_emit[t * Uk + (u - 1)];
                    a = lae(x, y);
                }
                if (u == yl && t == fl - 1)
                    g_ll[b] = a + s_blank[(fl - 1) * U1k + u];
            } else if (t == 0 && u >= 1) {
                a = left + s_emit[u - 1];   // emit[0][u-1]
                if (u == yl && fl == 1)     // (can't occur: fl>=T/2, but keep exact)
                    g_ll[b] = a + s_blank[u];
            }
            comm[(1 - p) * 66 + u] = a;
        }
        __syncthreads();
        p ^= 1;
    }
}

// ---------------------------------------------------------------------------
// Kernel 3: loss = -mean(ll)
// ---------------------------------------------------------------------------
__global__ void rnnt_finalize_kernel(float* __restrict__ out) {
    float s = 0.f;
#pragma unroll
    for (int b = 0; b < Bk; ++b) s += g_ll[b];
    out[0] = -s / (float)Bk;
}

extern "C" void kernel_launch(void* const* d_in, const int* in_sizes, int n_in,
                              void* d_out, int out_size)
{
    const float* logits = (const float*)d_in[0];
    const int*   labels = (const int*)d_in[1];
    const int*   f_len  = (const int*)d_in[2];
    const int*   y_len  = (const int*)d_in[3];

    const int rows = Bk * Tk * U1k;             // 133120 rows, one warp each
    const int blocks = (rows * 32 + 255) / 256; // 8 warps per block

    rnnt_softmax_kernel<<<blocks, 256>>>(logits, labels, y_len);

    const size_t smem = (size_t)(Tk * U1k + Tk * Uk + 2 * 66) * sizeof(float);
    cudaFuncSetAttribute(rnnt_dp_kernel,
                         cudaFuncAttributeMaxDynamicSharedMemorySize, (int)smem);
    rnnt_dp_kernel<<<Bk, 128, smem>>>(f_len, y_len);

    rnnt_finalize_kernel<<<1, 1>>>((float*)d_out);
}